// round 7
// baseline (speedup 1.0000x reference)
#include <cuda_runtime.h>
#include <cuda_bf16.h>
#include <math.h>
#include <stdint.h>

// Problem constants
#define BATCH 4
#define CDIM  512
#define TDIM  2048
#define NCB   4096
#define HH    4
#define KSPLIT (3 * CDIM)          // 1536: A=[hi|lo|hi], B=[hi|hi|lo]  (bf16)
#define CSCALE 0.04419417382415922f   // 1/(sqrt(128)*sqrt(4))

#define NBLOCKS (NCB / 128)        // 32 partial-argmax slices

// ---------------- scratch (device globals; no runtime allocation) -----------
__device__ __nv_bfloat16 g_AcbS[(size_t)NCB * KSPLIT];         // cb split [hi|lo|hi]
__device__ __nv_bfloat16 g_HsS [(size_t)BATCH * TDIM * KSPLIT];// hs^T split [hi|lo|hi]
__device__ __nv_bfloat16 g_WTS [3][(size_t)CDIM * KSPLIT];     // Wq,Wk,Wv^T [hi|hi|lo]
__device__ __nv_bfloat16 g_KpS[(size_t)NCB * KSPLIT];          // K' split [hi|lo|hi]
__device__ __nv_bfloat16 g_QgS[(size_t)BATCH * TDIM * KSPLIT]; // Qg split [hi|hi|lo]
__device__ float g_V [(size_t)NCB * CDIM];
__device__ float g_cg[(size_t)BATCH * TDIM * HH];
__device__ int   g_idx[(size_t)BATCH * TDIM];
__device__ float g_pmax[NBLOCKS * BATCH * TDIM];
__device__ int   g_pidx[NBLOCKS * BATCH * TDIM];

// ======================= helpers ============================================
#define SMEM_SWIZZLE_128B(off) ((off) ^ (((off) >> 3) & 0x70))
#define CP_ASYNC16(dst, src) \
    asm volatile("cp.async.cg.shared.global [%0], [%1], 16;" :: "r"(dst), "l"(src))
#define CP_ASYNC_COMMIT() asm volatile("cp.async.commit_group;" ::: "memory")

__device__ __forceinline__ uint32_t smem_to_u32(const void* p) {
    uint32_t a;
    asm("{ .reg .u64 t; cvta.to.shared.u64 t, %1; cvt.u32.u64 %0, t; }"
        : "=r"(a) : "l"(p));
    return a;
}
__device__ __forceinline__ void ldsm_x4(uint32_t& r0, uint32_t& r1, uint32_t& r2,
                                        uint32_t& r3, uint32_t addr) {
    asm volatile("ldmatrix.sync.aligned.m8n8.x4.shared.b16 {%0,%1,%2,%3}, [%4];"
                 : "=r"(r0), "=r"(r1), "=r"(r2), "=r"(r3) : "r"(addr));
}
__device__ __forceinline__ void mma16816(float* c, uint32_t a0, uint32_t a1,
                                         uint32_t a2, uint32_t a3,
                                         uint32_t b0, uint32_t b1) {
    asm volatile(
        "mma.sync.aligned.m16n8k16.row.col.f32.bf16.bf16.f32 "
        "{%0,%1,%2,%3}, {%4,%5,%6,%7}, {%8,%9}, {%0,%1,%2,%3};"
        : "+f"(c[0]), "+f"(c[1]), "+f"(c[2]), "+f"(c[3])
        : "r"(a0), "r"(a1), "r"(a2), "r"(a3), "r"(b0), "r"(b1));
}
__device__ __forceinline__ void split2bf(float v0, float v1, unsigned& hu, unsigned& lu) {
    __nv_bfloat16 h0 = __float2bfloat16(v0), h1 = __float2bfloat16(v1);
    float r0 = v0 - __bfloat162float(h0), r1 = v1 - __bfloat162float(h1);
    __nv_bfloat16 l0 = __float2bfloat16(r0), l1 = __float2bfloat16(r1);
    __nv_bfloat162 ph = __halves2bfloat162(h0, h1);
    __nv_bfloat162 pl = __halves2bfloat162(l0, l1);
    hu = *reinterpret_cast<unsigned*>(&ph);
    lu = *reinterpret_cast<unsigned*>(&pl);
}
__device__ __forceinline__ void split1bf(float v, __nv_bfloat16& h, __nv_bfloat16& l) {
    h = __float2bfloat16(v);
    l = __float2bfloat16(v - __bfloat162float(h));
}

// ============ canonical K=1536 bf16 mma core, tile 128(M) x 256(N) ==========
// A: 128 rows K-major (3072 B/row); B: 256 rows K-major.
// 8 warps as 2(m) x 4(n); warp tile 64 x 64.
// acc[mi*8+nj][f]: row r = wm*64+mi*16+(lane>>2)+(f>=2?8:0),
//                  col c = wn*64+nj*8+2*(lane&3)+(f&1)
#define GEMM_STAGE  49152                    // A 16KB + B 32KB
#define GEMM_SMEM   (3 * GEMM_STAGE)         // 147456
#define GEMM_CHUNKS (KSPLIT / 64)            // 24

__device__ __forceinline__ void gemm1536_core256(const char* Abase, const char* Bbase,
                                                 uint32_t sb, int tid,
                                                 float (&acc)[32][4]) {
    const int lane = tid & 31;
    const int wid  = tid >> 5;
    const int wm = wid & 1, wn = wid >> 1;

    #define GISSUE(c) do { \
        int _s = (c) % 3; \
        uint32_t _as = sb + _s * GEMM_STAGE; \
        uint32_t _bs = _as + 16384; \
        size_t _ko = (size_t)(c) * 128; \
        _Pragma("unroll") \
        for (int _i = 0; _i < 4; _i++) { \
            int _u = tid + _i * 256; \
            int _r = _u >> 3, _c16 = (_u & 7) * 16; \
            CP_ASYNC16(_as + SMEM_SWIZZLE_128B(_r * 128 + _c16), \
                       Abase + (size_t)_r * 3072 + _ko + _c16); \
        } \
        _Pragma("unroll") \
        for (int _i = 0; _i < 8; _i++) { \
            int _u = tid + _i * 256; \
            int _r = _u >> 3, _c16 = (_u & 7) * 16; \
            CP_ASYNC16(_bs + SMEM_SWIZZLE_128B(_r * 128 + _c16), \
                       Bbase + (size_t)_r * 3072 + _ko + _c16); \
        } \
        CP_ASYNC_COMMIT(); \
    } while (0)

    GISSUE(0);
    GISSUE(1);

    for (int c = 0; c < GEMM_CHUNKS; c++) {
        if (c < GEMM_CHUNKS - 1) asm volatile("cp.async.wait_group 1;" ::: "memory");
        else                     asm volatile("cp.async.wait_group 0;" ::: "memory");
        __syncthreads();
        if (c + 2 < GEMM_CHUNKS) GISSUE(c + 2);   // buffer (c-1)%3 is free

        uint32_t As = sb + (c % 3) * GEMM_STAGE;
        uint32_t Bs = As + 16384;

        #pragma unroll
        for (int kk = 0; kk < 4; kk++) {
            uint32_t a[4][4];
            #pragma unroll
            for (int mi = 0; mi < 4; mi++) {
                int row = wm * 64 + mi * 16 + (lane & 15);
                int u   = kk * 2 + (lane >> 4);
                ldsm_x4(a[mi][0], a[mi][1], a[mi][2], a[mi][3],
                        As + row * 128 + ((u ^ (row & 7)) << 4));
            }
            uint32_t bf[4][4];
            #pragma unroll
            for (int nf = 0; nf < 4; nf++) {
                int row = wn * 64 + nf * 16 + ((lane >> 4) << 3) + (lane & 7);
                int u   = kk * 2 + ((lane >> 3) & 1);
                ldsm_x4(bf[nf][0], bf[nf][1], bf[nf][2], bf[nf][3],
                        Bs + row * 128 + ((u ^ (row & 7)) << 4));
            }
            #pragma unroll
            for (int mi = 0; mi < 4; mi++)
                #pragma unroll
                for (int nj = 0; nj < 8; nj++)
                    mma16816(acc[mi * 8 + nj],
                             a[mi][0], a[mi][1], a[mi][2], a[mi][3],
                             bf[nj >> 1][(nj & 1) * 2], bf[nj >> 1][(nj & 1) * 2 + 1]);
        }
    }
    #undef GISSUE
}

// ===================== prep kernels =========================================
// cb [N,512] fp32 -> g_AcbS [N,1536] (hi|lo|hi)
__global__ void split_cb_kernel(const float* __restrict__ cb) {
    int idx = blockIdx.x * 256 + threadIdx.x;      // N*128 total
    int n  = idx >> 7;
    int c4 = (idx & 127) * 4;
    float4 v = *(const float4*)(cb + (size_t)n * CDIM + c4);
    unsigned h0, l0, h1, l1;
    split2bf(v.x, v.y, h0, l0);
    split2bf(v.z, v.w, h1, l1);
    __nv_bfloat16* op = g_AcbS + (size_t)n * KSPLIT + c4;
    *(uint2*)(op)        = make_uint2(h0, h1);
    *(uint2*)(op + 512)  = make_uint2(l0, l1);
    *(uint2*)(op + 1024) = make_uint2(h0, h1);
}

// W [512 in,512 out] fp32 -> g_WTS[z] [c][1536] (hi|hi|lo); z: 0=Wq 1=Wk 2=Wv
__global__ void wsplit_kernel(const float* __restrict__ Wq,
                              const float* __restrict__ Wk,
                              const float* __restrict__ Wv) {
    const float* W = (blockIdx.z == 0) ? Wq : (blockIdx.z == 1) ? Wk : Wv;
    __shared__ float tile[32][33];
    int ci0 = blockIdx.y * 32, c0 = blockIdx.x * 32;
    int tx = threadIdx.x & 31, ty = threadIdx.x >> 5;     // ty 0..7
    #pragma unroll
    for (int k = 0; k < 4; k++)
        tile[ty + 8 * k][tx] = W[(size_t)(ci0 + ty + 8 * k) * CDIM + c0 + tx];
    __syncthreads();
    __nv_bfloat16* base = g_WTS[blockIdx.z];
    #pragma unroll
    for (int k = 0; k < 4; k++) {
        int c = c0 + ty + 8 * k;
        float v = tile[tx][ty + 8 * k];
        __nv_bfloat16 h, l; split1bf(v, h, l);
        __nv_bfloat16* op = base + (size_t)c * KSPLIT + ci0 + tx;
        op[0] = h; op[512] = h; op[1024] = l;
    }
}

// hidden [B,512,2048] fp32 -> g_HsS [(b*T+t)][1536] (hi|lo|hi)
__global__ void hsplit_kernel(const float* __restrict__ hidden) {
    int b = blockIdx.z;
    __shared__ float tile[32][33];
    int ci0 = blockIdx.y * 32, t0 = blockIdx.x * 32;
    int tx = threadIdx.x & 31, ty = threadIdx.x >> 5;
    const float* hp = hidden + (size_t)b * CDIM * TDIM;
    #pragma unroll
    for (int k = 0; k < 4; k++)
        tile[ty + 8 * k][tx] = hp[(size_t)(ci0 + ty + 8 * k) * TDIM + t0 + tx];
    __syncthreads();
    #pragma unroll
    for (int k = 0; k < 4; k++) {
        int t = t0 + ty + 8 * k;
        float v = tile[tx][ty + 8 * k];
        __nv_bfloat16 h, l; split1bf(v, h, l);
        __nv_bfloat16* op = g_HsS + ((size_t)b * TDIM + t) * KSPLIT + ci0 + tx;
        op[0] = h; op[512] = l; op[1024] = h;
    }
}

// cg[bt][h] = sum_ci (hs_hi+hs_lo)(ci) * Wp[ci][h] + bp[h]
__global__ void cg2_kernel(const float* __restrict__ Wp, const float* __restrict__ bp) {
    __shared__ float sWp[CDIM * HH];
    #pragma unroll
    for (int i = 0; i < 8; i++)
        sWp[threadIdx.x + i * 256] = Wp[threadIdx.x + i * 256];
    __syncthreads();
    int w = threadIdx.x >> 5, lane = threadIdx.x & 31;
    int bt = blockIdx.x * 8 + w;
    const __nv_bfloat16* row = g_HsS + (size_t)bt * KSPLIT;
    float a0 = 0, a1 = 0, a2 = 0, a3 = 0;
    for (int ci = lane; ci < CDIM; ci += 32) {
        float x = __bfloat162float(row[ci]) + __bfloat162float(row[512 + ci]);
        a0 += x * sWp[ci * 4 + 0];
        a1 += x * sWp[ci * 4 + 1];
        a2 += x * sWp[ci * 4 + 2];
        a3 += x * sWp[ci * 4 + 3];
    }
    #pragma unroll
    for (int off = 16; off; off >>= 1) {
        a0 += __shfl_xor_sync(0xffffffff, a0, off);
        a1 += __shfl_xor_sync(0xffffffff, a1, off);
        a2 += __shfl_xor_sync(0xffffffff, a2, off);
        a3 += __shfl_xor_sync(0xffffffff, a3, off);
    }
    if (lane == 0) {
        g_cg[(size_t)bt * 4 + 0] = a0 + bp[0];
        g_cg[(size_t)bt * 4 + 1] = a1 + bp[1];
        g_cg[(size_t)bt * 4 + 2] = a2 + bp[2];
        g_cg[(size_t)bt * 4 + 3] = a3 + bp[3];
    }
}

// ===================== merged projection GEMMs (tensor) =====================
// grid (2, 128): y<32 -> K' ; 32<=y<64 -> V ; y>=64 -> Qg.  N tile = 256 cols.
__global__ __launch_bounds__(256, 1)
void gemm_proj_all(const float* __restrict__ bq, const float* __restrict__ bk,
                   const float* __restrict__ bv) {
    extern __shared__ __align__(1024) char smem[];
    const int tid = threadIdx.x;
    const int lane = tid & 31, wid = tid >> 5;
    const int wm = wid & 1, wn = wid >> 1;
    const int y = blockIdx.y;
    const int cBase = blockIdx.x * 256;
    const uint32_t sb = smem_to_u32(smem);

    const char* Abase;
    const char* Bbase;
    int rBase;
    int mode;           // 0=K', 1=V, 2=Qg
    if (y < 32)       { mode = 0; rBase = y * 128;
                        Abase = (const char*)(g_AcbS + (size_t)rBase * KSPLIT);
                        Bbase = (const char*)(g_WTS[1] + (size_t)cBase * KSPLIT); }
    else if (y < 64)  { mode = 1; rBase = (y - 32) * 128;
                        Abase = (const char*)(g_AcbS + (size_t)rBase * KSPLIT);
                        Bbase = (const char*)(g_WTS[2] + (size_t)cBase * KSPLIT); }
    else              { mode = 2; rBase = (y - 64) * 128;
                        Abase = (const char*)(g_HsS + (size_t)rBase * KSPLIT);
                        Bbase = (const char*)(g_WTS[0] + (size_t)cBase * KSPLIT); }

    float acc[32][4] = {};
    gemm1536_core256(Abase, Bbase, sb, tid, acc);

    if (mode == 0) {
        #pragma unroll
        for (int mi = 0; mi < 4; mi++)
            #pragma unroll
            for (int nj = 0; nj < 8; nj++) {
                float* A = acc[mi * 8 + nj];
                int r  = wm * 64 + mi * 16 + (lane >> 2);
                int cc = cBase + wn * 64 + nj * 8 + 2 * (lane & 3);
                float b0 = bk[cc], b1 = bk[cc + 1];
                unsigned h, l;
                split2bf(A[0] + b0, A[1] + b1, h, l);
                __nv_bfloat16* op = g_KpS + (size_t)(rBase + r) * KSPLIT + cc;
                *(unsigned*)(op) = h; *(unsigned*)(op + 512) = l; *(unsigned*)(op + 1024) = h;
                split2bf(A[2] + b0, A[3] + b1, h, l);
                op = g_KpS + (size_t)(rBase + r + 8) * KSPLIT + cc;
                *(unsigned*)(op) = h; *(unsigned*)(op + 512) = l; *(unsigned*)(op + 1024) = h;
            }
    } else if (mode == 1) {
        #pragma unroll
        for (int mi = 0; mi < 4; mi++)
            #pragma unroll
            for (int nj = 0; nj < 8; nj++) {
                float* A = acc[mi * 8 + nj];
                int r  = wm * 64 + mi * 16 + (lane >> 2);
                int cc = cBase + wn * 64 + nj * 8 + 2 * (lane & 3);
                float b0 = bv[cc], b1 = bv[cc + 1];
                *(float2*)(g_V + (size_t)(rBase + r) * CDIM + cc) =
                    make_float2(A[0] + b0, A[1] + b1);
                *(float2*)(g_V + (size_t)(rBase + r + 8) * CDIM + cc) =
                    make_float2(A[2] + b0, A[3] + b1);
            }
    } else {
        #pragma unroll
        for (int mi = 0; mi < 4; mi++)
            #pragma unroll
            for (int nj = 0; nj < 8; nj++) {
                float* A = acc[mi * 8 + nj];
                int r  = wm * 64 + mi * 16 + (lane >> 2);
                int cc = cBase + wn * 64 + nj * 8 + 2 * (lane & 3);
                int h = cc >> 7;                 // head of this 8-col group
                float b0 = bq[cc], b1 = bq[cc + 1];
                int bt0 = rBase + r, bt1 = rBase + r + 8;
                float g0 = g_cg[(size_t)bt0 * 4 + h] * CSCALE;
                float g1 = g_cg[(size_t)bt1 * 4 + h] * CSCALE;
                unsigned hh, ll;
                split2bf((A[0] + b0) * g0, (A[1] + b1) * g0, hh, ll);
                __nv_bfloat16* op = g_QgS + (size_t)bt0 * KSPLIT + cc;
                *(unsigned*)(op) = hh; *(unsigned*)(op + 512) = hh; *(unsigned*)(op + 1024) = ll;
                split2bf((A[2] + b0) * g1, (A[3] + b1) * g1, hh, ll);
                op = g_QgS + (size_t)bt1 * KSPLIT + cc;
                *(unsigned*)(op) = hh; *(unsigned*)(op + 512) = hh; *(unsigned*)(op + 1024) = ll;
            }
    }
}

// ===================== logits GEMM + fused argmax ===========================
__global__ __launch_bounds__(256, 1)
void gemm_logits_mma(float* __restrict__ out) {
    extern __shared__ __align__(1024) char smem[];
    const int tid  = threadIdx.x;
    const int wid  = tid >> 5, lane = tid & 31;
    const int wm   = wid & 1;
    const int wn   = wid >> 1;
    const int b     = blockIdx.z;
    const int nBase = blockIdx.y * 128;
    const int tBase = blockIdx.x * 256;
    const uint32_t sb = smem_to_u32(smem);

    float acc[32][4] = {};
    gemm1536_core256((const char*)(g_KpS + (size_t)nBase * KSPLIT),
                     (const char*)(g_QgS + ((size_t)b * TDIM + tBase) * KSPLIT),
                     sb, tid, acc);

    __syncthreads();   // smem free; safe to alias for argmax below

    // ---- write logits ----
    float* obase = out + (size_t)b * NCB * TDIM + (size_t)nBase * TDIM + tBase;
    #pragma unroll
    for (int mi = 0; mi < 4; mi++) {
        #pragma unroll
        for (int nj = 0; nj < 8; nj++) {
            float* A = acc[mi * 8 + nj];
            int r  = wm * 64 + mi * 16 + (lane >> 2);
            int cc = wn * 64 + nj * 8 + 2 * (lane & 3);
            *(float2*)(obase + (size_t)r * TDIM + cc)       = make_float2(A[0], A[1]);
            *(float2*)(obase + (size_t)(r + 8) * TDIM + cc) = make_float2(A[2], A[3]);
        }
    }

    // ---- fused argmax partial over this CTA's 128 rows (256 t cols) ----
    float mv[16]; int mi_[16];
    #pragma unroll
    for (int nj = 0; nj < 8; nj++) {
        #pragma unroll
        for (int cc = 0; cc < 2; cc++) {
            int key = nj * 2 + cc;
            float best = -INFINITY; int bidx = 0;
            #pragma unroll
            for (int mi = 0; mi < 4; mi++) {
                #pragma unroll
                for (int hf = 0; hf < 2; hf++) {
                    float v = acc[mi * 8 + nj][hf * 2 + cc];
                    int   ix = nBase + wm * 64 + mi * 16 + (lane >> 2) + hf * 8;
                    if (v > best || (v == best && ix < bidx)) { best = v; bidx = ix; }
                }
            }
            mv[key] = best; mi_[key] = bidx;
        }
    }
    #pragma unroll
    for (int off = 4; off < 32; off <<= 1) {
        #pragma unroll
        for (int key = 0; key < 16; key++) {
            float ov = __shfl_xor_sync(0xffffffff, mv[key], off);
            int   oi = __shfl_xor_sync(0xffffffff, mi_[key], off);
            if (ov > mv[key] || (ov == mv[key] && oi < mi_[key])) {
                mv[key] = ov; mi_[key] = oi;
            }
        }
    }
    float* sval = (float*)smem;               // [2][256]
    int*   sidx = (int*)(smem + 2 * 256 * 4); // [2][256]
    if (lane < 4) {
        #pragma unroll
        for (int nj = 0; nj < 8; nj++)
            #pragma unroll
            for (int cc = 0; cc < 2; cc++) {
                int col = wn * 64 + nj * 8 + 2 * lane + cc;
                sval[wm * 256 + col] = mv[nj * 2 + cc];
                sidx[wm * 256 + col] = mi_[nj * 2 + cc];
            }
    }
    __syncthreads();
    {
        float v0 = sval[tid],      v1 = sval[256 + tid];
        int   i0 = sidx[tid],      i1 = sidx[256 + tid];
        bool take1 = (v1 > v0) || (v1 == v0 && i1 < i0);
        size_t o = ((size_t)blockIdx.y * BATCH + b) * TDIM + tBase + tid;
        g_pmax[o] = take1 ? v1 : v0;
        g_pidx[o] = take1 ? i1 : i0;
    }
}

// ------------- fused final argmax (32 slices) + z_q gather ------------------
// grid (TDIM/32, BATCH), 256 threads. Phase 1: 32 threads finish argmax for
// this block's 32 t's. Phase 2: all 8 warps gather V rows.
__global__ void argmax_zq_kernel(float* __restrict__ idx_out, float* __restrict__ zq) {
    __shared__ int sIdx[32];
    int b = blockIdx.y;
    int t0 = blockIdx.x * 32;
    if (threadIdx.x < 32) {
        int t = t0 + threadIdx.x;
        float best = -INFINITY; int bi = 0x7fffffff;
        #pragma unroll
        for (int z = 0; z < NBLOCKS; z++) {
            float x = g_pmax[((size_t)z * BATCH + b) * TDIM + t];
            int  ii = g_pidx[((size_t)z * BATCH + b) * TDIM + t];
            if (x > best || (x == best && ii < bi)) { best = x; bi = ii; }
        }
        g_idx[b * TDIM + t] = bi;
        sIdx[threadIdx.x] = bi;
        idx_out[b * TDIM + t] = (float)bi;
    }
    __syncthreads();
    int lane = threadIdx.x & 31;
    int cgrp = threadIdx.x >> 5;
    int t = t0 + lane;
    int row = sIdx[lane];
    const float* v = g_V + (size_t)row * CDIM;
    float* o = zq + (size_t)b * CDIM * TDIM + t;
    int c0 = cgrp * 64;
    #pragma unroll 8
    for (int c = c0; c < c0 + 64; c++)
        o[(size_t)c * TDIM] = __ldg(&v[c]);
}

// ---------------- launcher --------------------------------------------------
extern "C" void kernel_launch(void* const* d_in, const int* in_sizes, int n_in,
                              void* d_out, int out_size) {
    const float* hidden = (const float*)d_in[0];  // [B,C,T]
    const float* cb     = (const float*)d_in[1];  // [N,C]
    const float* Wq = (const float*)d_in[2]; const float* bq = (const float*)d_in[3];
    const float* Wk = (const float*)d_in[4]; const float* bk = (const float*)d_in[5];
    const float* Wv = (const float*)d_in[6]; const float* bv = (const float*)d_in[7];
    const float* Wp = (const float*)d_in[8]; const float* bp = (const float*)d_in[9];

    float* out        = (float*)d_out;
    float* out_logits = out;                                       // B*N*T
    float* out_idx    = out + (size_t)BATCH * NCB * TDIM;          // B*T
    float* out_zq     = out_idx + (size_t)BATCH * TDIM;            // B*C*T

    cudaFuncSetAttribute(gemm_proj_all,
                         cudaFuncAttributeMaxDynamicSharedMemorySize, GEMM_SMEM);
    cudaFuncSetAttribute(gemm_logits_mma,
                         cudaFuncAttributeMaxDynamicSharedMemorySize, GEMM_SMEM);

    // prep: splits + transposes
    split_cb_kernel<<<NCB * 128 / 256, 256>>>(cb);
    wsplit_kernel<<<dim3(16, 16, 3), 256>>>(Wq, Wk, Wv);
    hsplit_kernel<<<dim3(TDIM / 32, CDIM / 32, BATCH), 256>>>(hidden);
    // head gates from transposed hidden
    cg2_kernel<<<BATCH * TDIM / 8, 256>>>(Wp, bp);
    // all projections in one launch (N tile 256)
    gemm_proj_all<<<dim3(2, 128), 256, GEMM_SMEM>>>(bq, bk, bv);
    // logits + fused argmax partials (tile 128x256)
    gemm_logits_mma<<<dim3(TDIM / 256, NCB / 128, BATCH), 256, GEMM_SMEM>>>(out_logits);
    // fused final argmax + z_q gather
    argmax_zq_kernel<<<dim3(TDIM / 32, BATCH), 256>>>(out_idx, out_zq);
}

// round 8
// speedup vs baseline: 1.0971x; 1.0971x over previous
#include <cuda_runtime.h>
#include <cuda_bf16.h>
#include <math.h>
#include <stdint.h>

// Problem constants
#define BATCH 4
#define CDIM  512
#define TDIM  2048
#define NCB   4096
#define HH    4
// Physical split storage: [hi|lo] = 1024 bf16 = 2048 B per row.
// Logical K = 1536 via chunk remap: A-side order hi,lo,hi ; B-side hi,hi,lo.
#define KPHYS 1024
#define ROWB  2048
#define CSCALE 0.04419417382415922f   // 1/(sqrt(128)*sqrt(4))

#define NBLOCKS (NCB / 128)        // 32 partial-argmax slices

// ---------------- scratch (device globals; no runtime allocation) -----------
__device__ __nv_bfloat16 g_AcbS[(size_t)NCB * KPHYS];          // cb split [hi|lo]
__device__ __nv_bfloat16 g_HsS [(size_t)BATCH * TDIM * KPHYS]; // hs^T split [hi|lo]
__device__ __nv_bfloat16 g_WTS [3][(size_t)CDIM * KPHYS];      // Wq,Wk,Wv^T [hi|lo]
__device__ __nv_bfloat16 g_KpS[(size_t)NCB * KPHYS];           // K' split [hi|lo]
__device__ __nv_bfloat16 g_QgS[(size_t)BATCH * TDIM * KPHYS];  // Qg split [hi|lo]
__device__ float g_V [(size_t)NCB * CDIM];
__device__ float g_cg[(size_t)BATCH * TDIM * HH];
__device__ int   g_idx[(size_t)BATCH * TDIM];
__device__ float g_pmax[NBLOCKS * BATCH * TDIM];
__device__ int   g_pidx[NBLOCKS * BATCH * TDIM];

// ======================= helpers ============================================
#define SMEM_SWIZZLE_128B(off) ((off) ^ (((off) >> 3) & 0x70))
#define CP_ASYNC16(dst, src) \
    asm volatile("cp.async.cg.shared.global [%0], [%1], 16;" :: "r"(dst), "l"(src))
#define CP_ASYNC_COMMIT() asm volatile("cp.async.commit_group;" ::: "memory")

__device__ __forceinline__ uint32_t smem_to_u32(const void* p) {
    uint32_t a;
    asm("{ .reg .u64 t; cvta.to.shared.u64 t, %1; cvt.u32.u64 %0, t; }"
        : "=r"(a) : "l"(p));
    return a;
}
__device__ __forceinline__ void ldsm_x4(uint32_t& r0, uint32_t& r1, uint32_t& r2,
                                        uint32_t& r3, uint32_t addr) {
    asm volatile("ldmatrix.sync.aligned.m8n8.x4.shared.b16 {%0,%1,%2,%3}, [%4];"
                 : "=r"(r0), "=r"(r1), "=r"(r2), "=r"(r3) : "r"(addr));
}
__device__ __forceinline__ void mma16816(float* c, uint32_t a0, uint32_t a1,
                                         uint32_t a2, uint32_t a3,
                                         uint32_t b0, uint32_t b1) {
    asm volatile(
        "mma.sync.aligned.m16n8k16.row.col.f32.bf16.bf16.f32 "
        "{%0,%1,%2,%3}, {%4,%5,%6,%7}, {%8,%9}, {%0,%1,%2,%3};"
        : "+f"(c[0]), "+f"(c[1]), "+f"(c[2]), "+f"(c[3])
        : "r"(a0), "r"(a1), "r"(a2), "r"(a3), "r"(b0), "r"(b1));
}
__device__ __forceinline__ void split2bf(float v0, float v1, unsigned& hu, unsigned& lu) {
    __nv_bfloat16 h0 = __float2bfloat16(v0), h1 = __float2bfloat16(v1);
    float r0 = v0 - __bfloat162float(h0), r1 = v1 - __bfloat162float(h1);
    __nv_bfloat16 l0 = __float2bfloat16(r0), l1 = __float2bfloat16(r1);
    __nv_bfloat162 ph = __halves2bfloat162(h0, h1);
    __nv_bfloat162 pl = __halves2bfloat162(l0, l1);
    hu = *reinterpret_cast<unsigned*>(&ph);
    lu = *reinterpret_cast<unsigned*>(&pl);
}
__device__ __forceinline__ void split1bf(float v, __nv_bfloat16& h, __nv_bfloat16& l) {
    h = __float2bfloat16(v);
    l = __float2bfloat16(v - __bfloat162float(h));
}

// ============ canonical logical-K=1536 bf16 mma core, tile 128x128 ==========
// A,B: 128 rows, physical [hi|lo] 2048 B each.
// Chunk c (0..23) loads A bytes aoff(c), B bytes boff(c):
//   A logical segs hi,lo,hi  -> aoff = (c<16 ? c : c-16)*128
//   B logical segs hi,hi,lo  -> boff = (c<8  ? c : c-8 )*128
// acc[mi*4+nj][f]: row r = wm*64+mi*16+(lane>>2)+(f>=2?8:0),
//                  col c = wn*32+nj*8+2*(lane&3)+(f&1)
#define GEMM_STAGE  32768                    // A 16KB + B 16KB
#define GEMM_SMEM   (3 * GEMM_STAGE)         // 98304
#define GEMM_CHUNKS 24

__device__ __forceinline__ void gemm1536_core(const char* Abase, const char* Bbase,
                                              uint32_t sb, int tid,
                                              float (&acc)[16][4]) {
    const int lane = tid & 31;
    const int wid  = tid >> 5;
    const int wm = wid & 1, wn = wid >> 1;

    #define GISSUE(c) do { \
        int _s = (c) % 3; \
        uint32_t _as = sb + _s * GEMM_STAGE; \
        uint32_t _bs = _as + 16384; \
        size_t _ka = (size_t)(((c) < 16 ? (c) : (c) - 16)) * 128; \
        size_t _kb = (size_t)(((c) < 8  ? (c) : (c) - 8 )) * 128; \
        _Pragma("unroll") \
        for (int _i = 0; _i < 4; _i++) { \
            int _u = tid + _i * 256; \
            int _r = _u >> 3, _c16 = (_u & 7) * 16; \
            CP_ASYNC16(_as + SMEM_SWIZZLE_128B(_r * 128 + _c16), \
                       Abase + (size_t)_r * ROWB + _ka + _c16); \
        } \
        _Pragma("unroll") \
        for (int _i = 0; _i < 4; _i++) { \
            int _u = tid + _i * 256; \
            int _r = _u >> 3, _c16 = (_u & 7) * 16; \
            CP_ASYNC16(_bs + SMEM_SWIZZLE_128B(_r * 128 + _c16), \
                       Bbase + (size_t)_r * ROWB + _kb + _c16); \
        } \
        CP_ASYNC_COMMIT(); \
    } while (0)

    GISSUE(0);
    GISSUE(1);

    for (int c = 0; c < GEMM_CHUNKS; c++) {
        if (c < GEMM_CHUNKS - 1) asm volatile("cp.async.wait_group 1;" ::: "memory");
        else                     asm volatile("cp.async.wait_group 0;" ::: "memory");
        __syncthreads();
        if (c + 2 < GEMM_CHUNKS) GISSUE(c + 2);   // buffer (c-1)%3 is free

        uint32_t As = sb + (c % 3) * GEMM_STAGE;
        uint32_t Bs = As + 16384;

        #pragma unroll
        for (int kk = 0; kk < 4; kk++) {
            uint32_t a[4][4];
            #pragma unroll
            for (int mi = 0; mi < 4; mi++) {
                int row = wm * 64 + mi * 16 + (lane & 15);
                int u   = kk * 2 + (lane >> 4);
                ldsm_x4(a[mi][0], a[mi][1], a[mi][2], a[mi][3],
                        As + row * 128 + ((u ^ (row & 7)) << 4));
            }
            uint32_t bf[2][4];
            #pragma unroll
            for (int nf = 0; nf < 2; nf++) {
                int row = wn * 32 + nf * 16 + ((lane >> 4) << 3) + (lane & 7);
                int u   = kk * 2 + ((lane >> 3) & 1);
                ldsm_x4(bf[nf][0], bf[nf][1], bf[nf][2], bf[nf][3],
                        Bs + row * 128 + ((u ^ (row & 7)) << 4));
            }
            #pragma unroll
            for (int mi = 0; mi < 4; mi++)
                #pragma unroll
                for (int nj = 0; nj < 4; nj++)
                    mma16816(acc[mi * 4 + nj],
                             a[mi][0], a[mi][1], a[mi][2], a[mi][3],
                             bf[nj >> 1][(nj & 1) * 2], bf[nj >> 1][(nj & 1) * 2 + 1]);
        }
    }
    #undef GISSUE
}

// ===================== prep kernels =========================================
// cb [N,512] fp32 -> g_AcbS [N,1024] (hi|lo)
__global__ void split_cb_kernel(const float* __restrict__ cb) {
    int idx = blockIdx.x * 256 + threadIdx.x;      // N*128 total
    int n  = idx >> 7;
    int c4 = (idx & 127) * 4;
    float4 v = *(const float4*)(cb + (size_t)n * CDIM + c4);
    unsigned h0, l0, h1, l1;
    split2bf(v.x, v.y, h0, l0);
    split2bf(v.z, v.w, h1, l1);
    __nv_bfloat16* op = g_AcbS + (size_t)n * KPHYS + c4;
    *(uint2*)(op)       = make_uint2(h0, h1);
    *(uint2*)(op + 512) = make_uint2(l0, l1);
}

// W [512 in,512 out] fp32 -> g_WTS[z] [c][1024] (hi|lo); z: 0=Wq 1=Wk 2=Wv
__global__ void wsplit_kernel(const float* __restrict__ Wq,
                              const float* __restrict__ Wk,
                              const float* __restrict__ Wv) {
    const float* W = (blockIdx.z == 0) ? Wq : (blockIdx.z == 1) ? Wk : Wv;
    __shared__ float tile[32][33];
    int ci0 = blockIdx.y * 32, c0 = blockIdx.x * 32;
    int tx = threadIdx.x & 31, ty = threadIdx.x >> 5;     // ty 0..7
    #pragma unroll
    for (int k = 0; k < 4; k++)
        tile[ty + 8 * k][tx] = W[(size_t)(ci0 + ty + 8 * k) * CDIM + c0 + tx];
    __syncthreads();
    __nv_bfloat16* base = g_WTS[blockIdx.z];
    #pragma unroll
    for (int k = 0; k < 4; k++) {
        int c = c0 + ty + 8 * k;
        float v = tile[tx][ty + 8 * k];
        __nv_bfloat16 h, l; split1bf(v, h, l);
        __nv_bfloat16* op = base + (size_t)c * KPHYS + ci0 + tx;
        op[0] = h; op[512] = l;
    }
}

// hidden [B,512,2048] fp32 -> g_HsS [(b*T+t)][1024] (hi|lo)
__global__ void hsplit_kernel(const float* __restrict__ hidden) {
    int b = blockIdx.z;
    __shared__ float tile[32][33];
    int ci0 = blockIdx.y * 32, t0 = blockIdx.x * 32;
    int tx = threadIdx.x & 31, ty = threadIdx.x >> 5;
    const float* hp = hidden + (size_t)b * CDIM * TDIM;
    #pragma unroll
    for (int k = 0; k < 4; k++)
        tile[ty + 8 * k][tx] = hp[(size_t)(ci0 + ty + 8 * k) * TDIM + t0 + tx];
    __syncthreads();
    #pragma unroll
    for (int k = 0; k < 4; k++) {
        int t = t0 + ty + 8 * k;
        float v = tile[tx][ty + 8 * k];
        __nv_bfloat16 h, l; split1bf(v, h, l);
        __nv_bfloat16* op = g_HsS + ((size_t)b * TDIM + t) * KPHYS + ci0 + tx;
        op[0] = h; op[512] = l;
    }
}

// cg[bt][h] = sum_ci (hs_hi+hs_lo)(ci) * Wp[ci][h] + bp[h]
__global__ void cg2_kernel(const float* __restrict__ Wp, const float* __restrict__ bp) {
    __shared__ float sWp[CDIM * HH];
    #pragma unroll
    for (int i = 0; i < 8; i++)
        sWp[threadIdx.x + i * 256] = Wp[threadIdx.x + i * 256];
    __syncthreads();
    int w = threadIdx.x >> 5, lane = threadIdx.x & 31;
    int bt = blockIdx.x * 8 + w;
    const __nv_bfloat16* row = g_HsS + (size_t)bt * KPHYS;
    float a0 = 0, a1 = 0, a2 = 0, a3 = 0;
    for (int ci = lane; ci < CDIM; ci += 32) {
        float x = __bfloat162float(row[ci]) + __bfloat162float(row[512 + ci]);
        a0 += x * sWp[ci * 4 + 0];
        a1 += x * sWp[ci * 4 + 1];
        a2 += x * sWp[ci * 4 + 2];
        a3 += x * sWp[ci * 4 + 3];
    }
    #pragma unroll
    for (int off = 16; off; off >>= 1) {
        a0 += __shfl_xor_sync(0xffffffff, a0, off);
        a1 += __shfl_xor_sync(0xffffffff, a1, off);
        a2 += __shfl_xor_sync(0xffffffff, a2, off);
        a3 += __shfl_xor_sync(0xffffffff, a3, off);
    }
    if (lane == 0) {
        g_cg[(size_t)bt * 4 + 0] = a0 + bp[0];
        g_cg[(size_t)bt * 4 + 1] = a1 + bp[1];
        g_cg[(size_t)bt * 4 + 2] = a2 + bp[2];
        g_cg[(size_t)bt * 4 + 3] = a3 + bp[3];
    }
}

// ===================== merged projection GEMMs (tensor) =====================
// grid (4, 128): y<32 -> K' ; 32<=y<64 -> V ; y>=64 -> Qg.  Tile 128x128.
__global__ __launch_bounds__(256, 2)
void gemm_proj_all(const float* __restrict__ bq, const float* __restrict__ bk,
                   const float* __restrict__ bv) {
    extern __shared__ __align__(1024) char smem[];
    const int tid = threadIdx.x;
    const int lane = tid & 31, wid = tid >> 5;
    const int wm = wid & 1, wn = wid >> 1;
    const int y = blockIdx.y;
    const int cBase = blockIdx.x * 128;
    const uint32_t sb = smem_to_u32(smem);

    const char* Abase;
    const char* Bbase;
    int rBase;
    int mode;           // 0=K', 1=V, 2=Qg
    if (y < 32)       { mode = 0; rBase = y * 128;
                        Abase = (const char*)(g_AcbS + (size_t)rBase * KPHYS);
                        Bbase = (const char*)(g_WTS[1] + (size_t)cBase * KPHYS); }
    else if (y < 64)  { mode = 1; rBase = (y - 32) * 128;
                        Abase = (const char*)(g_AcbS + (size_t)rBase * KPHYS);
                        Bbase = (const char*)(g_WTS[2] + (size_t)cBase * KPHYS); }
    else              { mode = 2; rBase = (y - 64) * 128;
                        Abase = (const char*)(g_HsS + (size_t)rBase * KPHYS);
                        Bbase = (const char*)(g_WTS[0] + (size_t)cBase * KPHYS); }

    float acc[16][4] = {};
    gemm1536_core(Abase, Bbase, sb, tid, acc);

    if (mode == 0) {
        #pragma unroll
        for (int mi = 0; mi < 4; mi++)
            #pragma unroll
            for (int nj = 0; nj < 4; nj++) {
                float* A = acc[mi * 4 + nj];
                int r  = wm * 64 + mi * 16 + (lane >> 2);
                int cc = cBase + wn * 32 + nj * 8 + 2 * (lane & 3);
                float b0 = bk[cc], b1 = bk[cc + 1];
                unsigned h, l;
                split2bf(A[0] + b0, A[1] + b1, h, l);
                __nv_bfloat16* op = g_KpS + (size_t)(rBase + r) * KPHYS + cc;
                *(unsigned*)(op) = h; *(unsigned*)(op + 512) = l;
                split2bf(A[2] + b0, A[3] + b1, h, l);
                op = g_KpS + (size_t)(rBase + r + 8) * KPHYS + cc;
                *(unsigned*)(op) = h; *(unsigned*)(op + 512) = l;
            }
    } else if (mode == 1) {
        #pragma unroll
        for (int mi = 0; mi < 4; mi++)
            #pragma unroll
            for (int nj = 0; nj < 4; nj++) {
                float* A = acc[mi * 4 + nj];
                int r  = wm * 64 + mi * 16 + (lane >> 2);
                int cc = cBase + wn * 32 + nj * 8 + 2 * (lane & 3);
                float b0 = bv[cc], b1 = bv[cc + 1];
                *(float2*)(g_V + (size_t)(rBase + r) * CDIM + cc) =
                    make_float2(A[0] + b0, A[1] + b1);
                *(float2*)(g_V + (size_t)(rBase + r + 8) * CDIM + cc) =
                    make_float2(A[2] + b0, A[3] + b1);
            }
    } else {
        const int h = blockIdx.x;          // 128-wide col tile == one head
        #pragma unroll
        for (int mi = 0; mi < 4; mi++)
            #pragma unroll
            for (int nj = 0; nj < 4; nj++) {
                float* A = acc[mi * 4 + nj];
                int r  = wm * 64 + mi * 16 + (lane >> 2);
                int cc = cBase + wn * 32 + nj * 8 + 2 * (lane & 3);
                float b0 = bq[cc], b1 = bq[cc + 1];
                int bt0 = rBase + r, bt1 = rBase + r + 8;
                float g0 = g_cg[(size_t)bt0 * 4 + h] * CSCALE;
                float g1 = g_cg[(size_t)bt1 * 4 + h] * CSCALE;
                unsigned hh, ll;
                split2bf((A[0] + b0) * g0, (A[1] + b1) * g0, hh, ll);
                __nv_bfloat16* op = g_QgS + (size_t)bt0 * KPHYS + cc;
                *(unsigned*)(op) = hh; *(unsigned*)(op + 512) = ll;
                split2bf((A[2] + b0) * g1, (A[3] + b1) * g1, hh, ll);
                op = g_QgS + (size_t)bt1 * KPHYS + cc;
                *(unsigned*)(op) = hh; *(unsigned*)(op + 512) = ll;
            }
    }
}

// ===================== logits GEMM + fused argmax ===========================
__global__ __launch_bounds__(256, 2)
void gemm_logits_mma(float* __restrict__ out) {
    extern __shared__ __align__(1024) char smem[];
    const int tid  = threadIdx.x;
    const int wid  = tid >> 5, lane = tid & 31;
    const int wm   = wid & 1;
    const int wn   = wid >> 1;
    const int b     = blockIdx.z;
    const int nBase = blockIdx.y * 128;
    const int tBase = blockIdx.x * 128;
    const uint32_t sb = smem_to_u32(smem);

    float acc[16][4] = {};
    gemm1536_core((const char*)(g_KpS + (size_t)nBase * KPHYS),
                  (const char*)(g_QgS + ((size_t)b * TDIM + tBase) * KPHYS),
                  sb, tid, acc);

    __syncthreads();   // smem free; safe to alias for argmax below

    // ---- write logits ----
    float* obase = out + (size_t)b * NCB * TDIM + (size_t)nBase * TDIM + tBase;
    #pragma unroll
    for (int mi = 0; mi < 4; mi++) {
        #pragma unroll
        for (int nj = 0; nj < 4; nj++) {
            float* A = acc[mi * 4 + nj];
            int r  = wm * 64 + mi * 16 + (lane >> 2);
            int cc = wn * 32 + nj * 8 + 2 * (lane & 3);
            *(float2*)(obase + (size_t)r * TDIM + cc)       = make_float2(A[0], A[1]);
            *(float2*)(obase + (size_t)(r + 8) * TDIM + cc) = make_float2(A[2], A[3]);
        }
    }

    // ---- fused argmax partial over this CTA's 128 rows ----
    float mv[8]; int mi_[8];
    #pragma unroll
    for (int nj = 0; nj < 4; nj++) {
        #pragma unroll
        for (int cc = 0; cc < 2; cc++) {
            int key = nj * 2 + cc;
            float best = -INFINITY; int bidx = 0;
            #pragma unroll
            for (int mi = 0; mi < 4; mi++) {
                #pragma unroll
                for (int hf = 0; hf < 2; hf++) {
                    float v = acc[mi * 4 + nj][hf * 2 + cc];
                    int   ix = nBase + wm * 64 + mi * 16 + (lane >> 2) + hf * 8;
                    if (v > best || (v == best && ix < bidx)) { best = v; bidx = ix; }
                }
            }
            mv[key] = best; mi_[key] = bidx;
        }
    }
    #pragma unroll
    for (int off = 4; off < 32; off <<= 1) {
        #pragma unroll
        for (int key = 0; key < 8; key++) {
            float ov = __shfl_xor_sync(0xffffffff, mv[key], off);
            int   oi = __shfl_xor_sync(0xffffffff, mi_[key], off);
            if (ov > mv[key] || (ov == mv[key] && oi < mi_[key])) {
                mv[key] = ov; mi_[key] = oi;
            }
        }
    }
    float* sval = (float*)smem;               // [2][128]
    int*   sidx = (int*)(smem + 2 * 128 * 4); // [2][128]
    if (lane < 4) {
        #pragma unroll
        for (int nj = 0; nj < 4; nj++)
            #pragma unroll
            for (int cc = 0; cc < 2; cc++) {
                int col = wn * 32 + nj * 8 + 2 * lane + cc;
                sval[wm * 128 + col] = mv[nj * 2 + cc];
                sidx[wm * 128 + col] = mi_[nj * 2 + cc];
            }
    }
    __syncthreads();
    if (tid < 128) {
        float v0 = sval[tid],      v1 = sval[128 + tid];
        int   i0 = sidx[tid],      i1 = sidx[128 + tid];
        bool take1 = (v1 > v0) || (v1 == v0 && i1 < i0);
        size_t o = ((size_t)blockIdx.y * BATCH + b) * TDIM + tBase + tid;
        g_pmax[o] = take1 ? v1 : v0;
        g_pidx[o] = take1 ? i1 : i0;
    }
}

// ------------- fused final argmax (32 slices) + z_q gather ------------------
__global__ void argmax_zq_kernel(float* __restrict__ idx_out, float* __restrict__ zq) {
    __shared__ int sIdx[32];
    int b = blockIdx.y;
    int t0 = blockIdx.x * 32;
    if (threadIdx.x < 32) {
        int t = t0 + threadIdx.x;
        float best = -INFINITY; int bi = 0x7fffffff;
        #pragma unroll
        for (int z = 0; z < NBLOCKS; z++) {
            float x = g_pmax[((size_t)z * BATCH + b) * TDIM + t];
            int  ii = g_pidx[((size_t)z * BATCH + b) * TDIM + t];
            if (x > best || (x == best && ii < bi)) { best = x; bi = ii; }
        }
        g_idx[b * TDIM + t] = bi;
        sIdx[threadIdx.x] = bi;
        idx_out[b * TDIM + t] = (float)bi;
    }
    __syncthreads();
    int lane = threadIdx.x & 31;
    int cgrp = threadIdx.x >> 5;
    int t = t0 + lane;
    int row = sIdx[lane];
    const float* v = g_V + (size_t)row * CDIM;
    float* o = zq + (size_t)b * CDIM * TDIM + t;
    int c0 = cgrp * 64;
    #pragma unroll 8
    for (int c = c0; c < c0 + 64; c++)
        o[(size_t)c * TDIM] = __ldg(&v[c]);
}

// ---------------- launcher --------------------------------------------------
extern "C" void kernel_launch(void* const* d_in, const int* in_sizes, int n_in,
                              void* d_out, int out_size) {
    const float* hidden = (const float*)d_in[0];  // [B,C,T]
    const float* cb     = (const float*)d_in[1];  // [N,C]
    const float* Wq = (const float*)d_in[2]; const float* bq = (const float*)d_in[3];
    const float* Wk = (const float*)d_in[4]; const float* bk = (const float*)d_in[5];
    const float* Wv = (const float*)d_in[6]; const float* bv = (const float*)d_in[7];
    const float* Wp = (const float*)d_in[8]; const float* bp = (const float*)d_in[9];

    float* out        = (float*)d_out;
    float* out_logits = out;                                       // B*N*T
    float* out_idx    = out + (size_t)BATCH * NCB * TDIM;          // B*T
    float* out_zq     = out_idx + (size_t)BATCH * TDIM;            // B*C*T

    cudaFuncSetAttribute(gemm_proj_all,
                         cudaFuncAttributeMaxDynamicSharedMemorySize, GEMM_SMEM);
    cudaFuncSetAttribute(gemm_logits_mma,
                         cudaFuncAttributeMaxDynamicSharedMemorySize, GEMM_SMEM);

    // prep: splits + transposes
    split_cb_kernel<<<NCB * 128 / 256, 256>>>(cb);
    wsplit_kernel<<<dim3(16, 16, 3), 256>>>(Wq, Wk, Wv);
    hsplit_kernel<<<dim3(TDIM / 32, CDIM / 32, BATCH), 256>>>(hidden);
    // head gates from transposed hidden
    cg2_kernel<<<BATCH * TDIM / 8, 256>>>(Wp, bp);
    // all projections in one launch (tile 128x128)
    gemm_proj_all<<<dim3(4, 128), 256, GEMM_SMEM>>>(bq, bk, bv);
    // logits + fused argmax partials
    gemm_logits_mma<<<dim3(TDIM / 128, NCB / 128, BATCH), 256, GEMM_SMEM>>>(out_logits);
    // fused final argmax + z_q gather
    argmax_zq_kernel<<<dim3(TDIM / 32, BATCH), 256>>>(out_idx, out_zq);
}

// round 9
// speedup vs baseline: 1.2393x; 1.1296x over previous
#include <cuda_runtime.h>
#include <cuda_bf16.h>
#include <math.h>
#include <stdint.h>

// Problem constants
#define BATCH 4
#define CDIM  512
#define TDIM  2048
#define NCB   4096
#define HH    4
// Physical split storage: [hi|lo] = 1024 bf16 = 2048 B per row.
// Logical K = 1536: products Ah*Bh + Al*Bh + Ah*Bl per 64-col ci-group.
#define KPHYS 1024
#define ROWB  2048
#define CSCALE 0.04419417382415922f   // 1/(sqrt(128)*sqrt(4))

#define NBLOCKS (NCB / 128)        // 32 partial-argmax slices

// ---------------- scratch (device globals; no runtime allocation) -----------
__device__ __nv_bfloat16 g_AcbS[(size_t)NCB * KPHYS];          // cb split [hi|lo]
__device__ __nv_bfloat16 g_HsS [(size_t)BATCH * TDIM * KPHYS]; // hs^T split [hi|lo]
__device__ __nv_bfloat16 g_WTS [3][(size_t)CDIM * KPHYS];      // Wq,Wk,Wv^T [hi|lo]
__device__ __nv_bfloat16 g_KpS[(size_t)NCB * KPHYS];           // K' split [hi|lo]
__device__ __nv_bfloat16 g_QgS[(size_t)BATCH * TDIM * KPHYS];  // Qg split [hi|lo]
__device__ float g_V [(size_t)NCB * CDIM];
__device__ float g_cg[(size_t)BATCH * TDIM * HH];   // includes bias
__device__ int   g_idx[(size_t)BATCH * TDIM];
__device__ float g_pmax[NBLOCKS * BATCH * TDIM];
__device__ int   g_pidx[NBLOCKS * BATCH * TDIM];

// ======================= helpers ============================================
#define SMEM_SWIZZLE_128B(off) ((off) ^ (((off) >> 3) & 0x70))
#define CP_ASYNC16(dst, src) \
    asm volatile("cp.async.cg.shared.global [%0], [%1], 16;" :: "r"(dst), "l"(src))
#define CP_ASYNC_COMMIT() asm volatile("cp.async.commit_group;" ::: "memory")

__device__ __forceinline__ uint32_t smem_to_u32(const void* p) {
    uint32_t a;
    asm("{ .reg .u64 t; cvta.to.shared.u64 t, %1; cvt.u32.u64 %0, t; }"
        : "=r"(a) : "l"(p));
    return a;
}
__device__ __forceinline__ void ldsm_x4(uint32_t& r0, uint32_t& r1, uint32_t& r2,
                                        uint32_t& r3, uint32_t addr) {
    asm volatile("ldmatrix.sync.aligned.m8n8.x4.shared.b16 {%0,%1,%2,%3}, [%4];"
                 : "=r"(r0), "=r"(r1), "=r"(r2), "=r"(r3) : "r"(addr));
}
__device__ __forceinline__ void mma16816(float* c, uint32_t a0, uint32_t a1,
                                         uint32_t a2, uint32_t a3,
                                         uint32_t b0, uint32_t b1) {
    asm volatile(
        "mma.sync.aligned.m16n8k16.row.col.f32.bf16.bf16.f32 "
        "{%0,%1,%2,%3}, {%4,%5,%6,%7}, {%8,%9}, {%0,%1,%2,%3};"
        : "+f"(c[0]), "+f"(c[1]), "+f"(c[2]), "+f"(c[3])
        : "r"(a0), "r"(a1), "r"(a2), "r"(a3), "r"(b0), "r"(b1));
}
__device__ __forceinline__ void split2bf(float v0, float v1, unsigned& hu, unsigned& lu) {
    __nv_bfloat16 h0 = __float2bfloat16(v0), h1 = __float2bfloat16(v1);
    float r0 = v0 - __bfloat162float(h0), r1 = v1 - __bfloat162float(h1);
    __nv_bfloat16 l0 = __float2bfloat16(r0), l1 = __float2bfloat16(r1);
    __nv_bfloat162 ph = __halves2bfloat162(h0, h1);
    __nv_bfloat162 pl = __halves2bfloat162(l0, l1);
    hu = *reinterpret_cast<unsigned*>(&ph);
    lu = *reinterpret_cast<unsigned*>(&pl);
}
__device__ __forceinline__ void split1bf(float v, __nv_bfloat16& h, __nv_bfloat16& l) {
    h = __float2bfloat16(v);
    l = __float2bfloat16(v - __bfloat162float(h));
}

// ====== canonical logical-K=1536 bf16 mma core with tile reuse ==============
// A,B: 128 rows, physical [hi|lo] 2048 B each. 8 ci-groups of 64 cols.
// Per group g: chunks r0=(Ah,Bh), r1=(Al,Bh), r2=(Ah,Bl).
// Loads L_j (j=0..15): phys chunk off = (j&1)? 8+(j>>1) : (j>>1); A+B -> stage j%3.
// Per g: stage sA=(2g)%3 holds (Ah_g,Bh_g); sB=(2g+1)%3 holds (Al_g,Bl_g).
// acc[mi*4+nj][f]: row r = wm*64+mi*16+(lane>>2)+(f>=2?8:0),
//                  col c = wn*32+nj*8+2*(lane&3)+(f&1)
#define GEMM_STAGE  32768                    // A 16KB + B 16KB
#define GEMM_SMEM   (3 * GEMM_STAGE)         // 98304

__device__ __forceinline__ void gemm1536_core(const char* Abase, const char* Bbase,
                                              uint32_t sb, int tid,
                                              float (&acc)[16][4]) {
    const int lane = tid & 31;
    const int wid  = tid >> 5;
    const int wm = wid & 1, wn = wid >> 1;

    #define GLOAD(j) do { \
        uint32_t _as = sb + ((j) % 3) * GEMM_STAGE; \
        uint32_t _bs = _as + 16384; \
        size_t _ko = (size_t)(((j) & 1) ? 8 + ((j) >> 1) : ((j) >> 1)) * 128; \
        _Pragma("unroll") \
        for (int _i = 0; _i < 4; _i++) { \
            int _u = tid + _i * 256; \
            int _r = _u >> 3, _c16 = (_u & 7) * 16; \
            CP_ASYNC16(_as + SMEM_SWIZZLE_128B(_r * 128 + _c16), \
                       Abase + (size_t)_r * ROWB + _ko + _c16); \
        } \
        _Pragma("unroll") \
        for (int _i = 0; _i < 4; _i++) { \
            int _u = tid + _i * 256; \
            int _r = _u >> 3, _c16 = (_u & 7) * 16; \
            CP_ASYNC16(_bs + SMEM_SWIZZLE_128B(_r * 128 + _c16), \
                       Bbase + (size_t)_r * ROWB + _ko + _c16); \
        } \
        CP_ASYNC_COMMIT(); \
    } while (0)

    #define MMA_CHUNK(Astage, Bstage) do { \
        uint32_t _As = sb + (Astage) * GEMM_STAGE; \
        uint32_t _Bs = sb + (Bstage) * GEMM_STAGE + 16384; \
        _Pragma("unroll") \
        for (int kk = 0; kk < 4; kk++) { \
            uint32_t a[4][4]; \
            _Pragma("unroll") \
            for (int mi = 0; mi < 4; mi++) { \
                int row = wm * 64 + mi * 16 + (lane & 15); \
                int u   = kk * 2 + (lane >> 4); \
                ldsm_x4(a[mi][0], a[mi][1], a[mi][2], a[mi][3], \
                        _As + row * 128 + ((u ^ (row & 7)) << 4)); \
            } \
            uint32_t bf[2][4]; \
            _Pragma("unroll") \
            for (int nf = 0; nf < 2; nf++) { \
                int row = wn * 32 + nf * 16 + ((lane >> 4) << 3) + (lane & 7); \
                int u   = kk * 2 + ((lane >> 3) & 1); \
                ldsm_x4(bf[nf][0], bf[nf][1], bf[nf][2], bf[nf][3], \
                        _Bs + row * 128 + ((u ^ (row & 7)) << 4)); \
            } \
            _Pragma("unroll") \
            for (int mi = 0; mi < 4; mi++) \
                _Pragma("unroll") \
                for (int nj = 0; nj < 4; nj++) \
                    mma16816(acc[mi * 4 + nj], \
                             a[mi][0], a[mi][1], a[mi][2], a[mi][3], \
                             bf[nj >> 1][(nj & 1) * 2], bf[nj >> 1][(nj & 1) * 2 + 1]); \
        } \
    } while (0)

    // Prologue: first three loads fill slots 0,1,2
    GLOAD(0); GLOAD(1); GLOAD(2);

    #pragma unroll
    for (int g = 0; g < 8; g++) {
        const int sA = (2 * g) % 3;
        const int sB = (2 * g + 1) % 3;

        // r0: (Ah_g, Bh_g) both in stage sA
        if (g == 0) asm volatile("cp.async.wait_group 2;" ::: "memory");
        else        asm volatile("cp.async.wait_group 0;" ::: "memory");
        __syncthreads();     // also proves all warps finished group g-1
        if (g >= 1) {
            GLOAD(2 * g + 1);                       // (Al_g, Bl_g) -> sB
            if (2 * g + 2 <= 15) GLOAD(2 * g + 2);  // (Ah_{g+1}, Bh_{g+1})
        }
        MMA_CHUNK(sA, sA);

        // r1: (Al_g, Bh_g) — A from sB, B from sA
        if (g == 7) asm volatile("cp.async.wait_group 0;" ::: "memory");
        else        asm volatile("cp.async.wait_group 1;" ::: "memory");
        __syncthreads();     // make L_{2g+1} data visible to all warps
        MMA_CHUNK(sB, sA);

        // r2: (Ah_g, Bl_g) — A from sA, B from sB; data already visible
        MMA_CHUNK(sA, sB);
    }
    #undef GLOAD
    #undef MMA_CHUNK
}

// ===================== prep kernels =========================================
// Merged: blockIdx.x < 2048 -> split cb ; else Wq/Wk/Wv transpose-split.
__global__ void prep_split_kernel(const float* __restrict__ cb,
                                  const float* __restrict__ Wq,
                                  const float* __restrict__ Wk,
                                  const float* __restrict__ Wv) {
    __shared__ float tile[32][33];
    int bx = blockIdx.x;
    if (bx < 2048) {
        // cb [N,512] fp32 -> g_AcbS [N,1024] (hi|lo)
        int idx = bx * 256 + threadIdx.x;
        int n  = idx >> 7;
        int c4 = (idx & 127) * 4;
        float4 v = *(const float4*)(cb + (size_t)n * CDIM + c4);
        unsigned h0, l0, h1, l1;
        split2bf(v.x, v.y, h0, l0);
        split2bf(v.z, v.w, h1, l1);
        __nv_bfloat16* op = g_AcbS + (size_t)n * KPHYS + c4;
        *(uint2*)(op)       = make_uint2(h0, h1);
        *(uint2*)(op + 512) = make_uint2(l0, l1);
    } else {
        int bid = bx - 2048;          // 0..767
        int z   = bid >> 8;           // 0..2
        int rem = bid & 255;
        int ci0 = (rem >> 4) * 32, c0 = (rem & 15) * 32;
        const float* W = (z == 0) ? Wq : (z == 1) ? Wk : Wv;
        int tx = threadIdx.x & 31, ty = threadIdx.x >> 5;
        #pragma unroll
        for (int k = 0; k < 4; k++)
            tile[ty + 8 * k][tx] = W[(size_t)(ci0 + ty + 8 * k) * CDIM + c0 + tx];
        __syncthreads();
        __nv_bfloat16* base = g_WTS[z];
        #pragma unroll
        for (int k = 0; k < 4; k++) {
            int c = c0 + ty + 8 * k;
            float v = tile[tx][ty + 8 * k];
            __nv_bfloat16 h, l; split1bf(v, h, l);
            __nv_bfloat16* op = base + (size_t)c * KPHYS + ci0 + tx;
            op[0] = h; op[512] = l;
        }
    }
}

// hidden [B,512,2048] fp32 -> g_HsS [(b*T+t)][1024] (hi|lo), fused cg.
// grid (TDIM/32, BATCH); block covers 32 t's x all 512 ci (16 sub-tiles).
// cg[bt][h] = sum_ci hidden[ci][t]*Wp[ci][h] + bp[h]   (deterministic order)
__global__ void hsplit_cg_kernel(const float* __restrict__ hidden,
                                 const float* __restrict__ Wp,
                                 const float* __restrict__ bp) {
    __shared__ float tile[32][33];
    __shared__ float sWp[CDIM * HH];
    int b  = blockIdx.y;
    int t0 = blockIdx.x * 32;
    int tx = threadIdx.x & 31, ty = threadIdx.x >> 5;
    const float* hp = hidden + (size_t)b * CDIM * TDIM;

    #pragma unroll
    for (int i = 0; i < 8; i++)
        sWp[threadIdx.x + i * 256] = Wp[threadIdx.x + i * 256];

    // per-thread cg ownership: tid<128: t_local = tid>>2, h = tid&3
    float cgacc = 0.f;
    int tl = threadIdx.x >> 2, hh = threadIdx.x & 3;

    for (int ci0 = 0; ci0 < CDIM; ci0 += 32) {
        __syncthreads();   // protect tile (and sWp on first iter)
        #pragma unroll
        for (int k = 0; k < 4; k++)
            tile[ty + 8 * k][tx] = hp[(size_t)(ci0 + ty + 8 * k) * TDIM + t0 + tx];
        __syncthreads();
        // transposed split store
        #pragma unroll
        for (int k = 0; k < 4; k++) {
            int t = t0 + ty + 8 * k;
            float v = tile[tx][ty + 8 * k];
            __nv_bfloat16 h, l; split1bf(v, h, l);
            __nv_bfloat16* op = g_HsS + ((size_t)b * TDIM + t) * KPHYS + ci0 + tx;
            op[0] = h; op[512] = l;
        }
        // cg partial (threads 0..127)
        if (threadIdx.x < 128) {
            #pragma unroll 8
            for (int ci = 0; ci < 32; ci++)
                cgacc += tile[ci][tl] * sWp[(ci0 + ci) * 4 + hh];
        }
    }
    if (threadIdx.x < 128) {
        int bt = b * TDIM + t0 + tl;
        g_cg[(size_t)bt * 4 + hh] = cgacc + bp[hh];
    }
}

// ===================== merged projection GEMMs (tensor) =====================
// grid (4, 128): y<32 -> K' ; 32<=y<64 -> V ; y>=64 -> Qg.  Tile 128x128.
__global__ __launch_bounds__(256, 2)
void gemm_proj_all(const float* __restrict__ bq, const float* __restrict__ bk,
                   const float* __restrict__ bv) {
    extern __shared__ __align__(1024) char smem[];
    const int tid = threadIdx.x;
    const int lane = tid & 31, wid = tid >> 5;
    const int wm = wid & 1, wn = wid >> 1;
    const int y = blockIdx.y;
    const int cBase = blockIdx.x * 128;
    const uint32_t sb = smem_to_u32(smem);

    const char* Abase;
    const char* Bbase;
    int rBase;
    int mode;           // 0=K', 1=V, 2=Qg
    if (y < 32)       { mode = 0; rBase = y * 128;
                        Abase = (const char*)(g_AcbS + (size_t)rBase * KPHYS);
                        Bbase = (const char*)(g_WTS[1] + (size_t)cBase * KPHYS); }
    else if (y < 64)  { mode = 1; rBase = (y - 32) * 128;
                        Abase = (const char*)(g_AcbS + (size_t)rBase * KPHYS);
                        Bbase = (const char*)(g_WTS[2] + (size_t)cBase * KPHYS); }
    else              { mode = 2; rBase = (y - 64) * 128;
                        Abase = (const char*)(g_HsS + (size_t)rBase * KPHYS);
                        Bbase = (const char*)(g_WTS[0] + (size_t)cBase * KPHYS); }

    float acc[16][4] = {};
    gemm1536_core(Abase, Bbase, sb, tid, acc);

    if (mode == 0) {
        #pragma unroll
        for (int mi = 0; mi < 4; mi++)
            #pragma unroll
            for (int nj = 0; nj < 4; nj++) {
                float* A = acc[mi * 4 + nj];
                int r  = wm * 64 + mi * 16 + (lane >> 2);
                int cc = cBase + wn * 32 + nj * 8 + 2 * (lane & 3);
                float b0 = bk[cc], b1 = bk[cc + 1];
                unsigned h, l;
                split2bf(A[0] + b0, A[1] + b1, h, l);
                __nv_bfloat16* op = g_KpS + (size_t)(rBase + r) * KPHYS + cc;
                *(unsigned*)(op) = h; *(unsigned*)(op + 512) = l;
                split2bf(A[2] + b0, A[3] + b1, h, l);
                op = g_KpS + (size_t)(rBase + r + 8) * KPHYS + cc;
                *(unsigned*)(op) = h; *(unsigned*)(op + 512) = l;
            }
    } else if (mode == 1) {
        #pragma unroll
        for (int mi = 0; mi < 4; mi++)
            #pragma unroll
            for (int nj = 0; nj < 4; nj++) {
                float* A = acc[mi * 4 + nj];
                int r  = wm * 64 + mi * 16 + (lane >> 2);
                int cc = cBase + wn * 32 + nj * 8 + 2 * (lane & 3);
                float b0 = bv[cc], b1 = bv[cc + 1];
                *(float2*)(g_V + (size_t)(rBase + r) * CDIM + cc) =
                    make_float2(A[0] + b0, A[1] + b1);
                *(float2*)(g_V + (size_t)(rBase + r + 8) * CDIM + cc) =
                    make_float2(A[2] + b0, A[3] + b1);
            }
    } else {
        const int h = blockIdx.x;          // 128-wide col tile == one head
        #pragma unroll
        for (int mi = 0; mi < 4; mi++)
            #pragma unroll
            for (int nj = 0; nj < 4; nj++) {
                float* A = acc[mi * 4 + nj];
                int r  = wm * 64 + mi * 16 + (lane >> 2);
                int cc = cBase + wn * 32 + nj * 8 + 2 * (lane & 3);
                float b0 = bq[cc], b1 = bq[cc + 1];
                int bt0 = rBase + r, bt1 = rBase + r + 8;
                float g0 = g_cg[(size_t)bt0 * 4 + h] * CSCALE;
                float g1 = g_cg[(size_t)bt1 * 4 + h] * CSCALE;
                unsigned hh, ll;
                split2bf((A[0] + b0) * g0, (A[1] + b1) * g0, hh, ll);
                __nv_bfloat16* op = g_QgS + (size_t)bt0 * KPHYS + cc;
                *(unsigned*)(op) = hh; *(unsigned*)(op + 512) = ll;
                split2bf((A[2] + b0) * g1, (A[3] + b1) * g1, hh, ll);
                op = g_QgS + (size_t)bt1 * KPHYS + cc;
                *(unsigned*)(op) = hh; *(unsigned*)(op + 512) = ll;
            }
    }
}

// ===================== logits GEMM + fused argmax ===========================
__global__ __launch_bounds__(256, 2)
void gemm_logits_mma(float* __restrict__ out) {
    extern __shared__ __align__(1024) char smem[];
    const int tid  = threadIdx.x;
    const int wid  = tid >> 5, lane = tid & 31;
    const int wm   = wid & 1;
    const int wn   = wid >> 1;
    const int b     = blockIdx.z;
    const int nBase = blockIdx.y * 128;
    const int tBase = blockIdx.x * 128;
    const uint32_t sb = smem_to_u32(smem);

    float acc[16][4] = {};
    gemm1536_core((const char*)(g_KpS + (size_t)nBase * KPHYS),
                  (const char*)(g_QgS + ((size_t)b * TDIM + tBase) * KPHYS),
                  sb, tid, acc);

    __syncthreads();   // smem free; safe to alias for argmax below

    // ---- write logits ----
    float* obase = out + (size_t)b * NCB * TDIM + (size_t)nBase * TDIM + tBase;
    #pragma unroll
    for (int mi = 0; mi < 4; mi++) {
        #pragma unroll
        for (int nj = 0; nj < 4; nj++) {
            float* A = acc[mi * 4 + nj];
            int r  = wm * 64 + mi * 16 + (lane >> 2);
            int cc = wn * 32 + nj * 8 + 2 * (lane & 3);
            *(float2*)(obase + (size_t)r * TDIM + cc)       = make_float2(A[0], A[1]);
            *(float2*)(obase + (size_t)(r + 8) * TDIM + cc) = make_float2(A[2], A[3]);
        }
    }

    // ---- fused argmax partial over this CTA's 128 rows ----
    float mv[8]; int mi_[8];
    #pragma unroll
    for (int nj = 0; nj < 4; nj++) {
        #pragma unroll
        for (int cc = 0; cc < 2; cc++) {
            int key = nj * 2 + cc;
            float best = -INFINITY; int bidx = 0;
            #pragma unroll
            for (int mi = 0; mi < 4; mi++) {
                #pragma unroll
                for (int hf = 0; hf < 2; hf++) {
                    float v = acc[mi * 4 + nj][hf * 2 + cc];
                    int   ix = nBase + wm * 64 + mi * 16 + (lane >> 2) + hf * 8;
                    if (v > best || (v == best && ix < bidx)) { best = v; bidx = ix; }
                }
            }
            mv[key] = best; mi_[key] = bidx;
        }
    }
    #pragma unroll
    for (int off = 4; off < 32; off <<= 1) {
        #pragma unroll
        for (int key = 0; key < 8; key++) {
            float ov = __shfl_xor_sync(0xffffffff, mv[key], off);
            int   oi = __shfl_xor_sync(0xffffffff, mi_[key], off);
            if (ov > mv[key] || (ov == mv[key] && oi < mi_[key])) {
                mv[key] = ov; mi_[key] = oi;
            }
        }
    }
    float* sval = (float*)smem;               // [2][128]
    int*   sidx = (int*)(smem + 2 * 128 * 4); // [2][128]
    if (lane < 4) {
        #pragma unroll
        for (int nj = 0; nj < 4; nj++)
            #pragma unroll
            for (int cc = 0; cc < 2; cc++) {
                int col = wn * 32 + nj * 8 + 2 * lane + cc;
                sval[wm * 128 + col] = mv[nj * 2 + cc];
                sidx[wm * 128 + col] = mi_[nj * 2 + cc];
            }
    }
    __syncthreads();
    if (tid < 128) {
        float v0 = sval[tid],      v1 = sval[128 + tid];
        int   i0 = sidx[tid],      i1 = sidx[128 + tid];
        bool take1 = (v1 > v0) || (v1 == v0 && i1 < i0);
        size_t o = ((size_t)blockIdx.y * BATCH + b) * TDIM + tBase + tid;
        g_pmax[o] = take1 ? v1 : v0;
        g_pidx[o] = take1 ? i1 : i0;
    }
}

// ------------- fused final argmax (32 slices) + z_q gather ------------------
__global__ void argmax_zq_kernel(float* __restrict__ idx_out, float* __restrict__ zq) {
    __shared__ int sIdx[32];
    int b = blockIdx.y;
    int t0 = blockIdx.x * 32;
    if (threadIdx.x < 32) {
        int t = t0 + threadIdx.x;
        float best = -INFINITY; int bi = 0x7fffffff;
        #pragma unroll
        for (int z = 0; z < NBLOCKS; z++) {
            float x = g_pmax[((size_t)z * BATCH + b) * TDIM + t];
            int  ii = g_pidx[((size_t)z * BATCH + b) * TDIM + t];
            if (x > best || (x == best && ii < bi)) { best = x; bi = ii; }
        }
        g_idx[b * TDIM + t] = bi;
        sIdx[threadIdx.x] = bi;
        idx_out[b * TDIM + t] = (float)bi;
    }
    __syncthreads();
    int lane = threadIdx.x & 31;
    int cgrp = threadIdx.x >> 5;
    int t = t0 + lane;
    int row = sIdx[lane];
    const float* v = g_V + (size_t)row * CDIM;
    float* o = zq + (size_t)b * CDIM * TDIM + t;
    int c0 = cgrp * 64;
    #pragma unroll 8
    for (int c = c0; c < c0 + 64; c++)
        o[(size_t)c * TDIM] = __ldg(&v[c]);
}

// ---------------- launcher --------------------------------------------------
extern "C" void kernel_launch(void* const* d_in, const int* in_sizes, int n_in,
                              void* d_out, int out_size) {
    const float* hidden = (const float*)d_in[0];  // [B,C,T]
    const float* cb     = (const float*)d_in[1];  // [N,C]
    const float* Wq = (const float*)d_in[2]; const float* bq = (const float*)d_in[3];
    const float* Wk = (const float*)d_in[4]; const float* bk = (const float*)d_in[5];
    const float* Wv = (const float*)d_in[6]; const float* bv = (const float*)d_in[7];
    const float* Wp = (const float*)d_in[8]; const float* bp = (const float*)d_in[9];

    float* out        = (float*)d_out;
    float* out_logits = out;                                       // B*N*T
    float* out_idx    = out + (size_t)BATCH * NCB * TDIM;          // B*T
    float* out_zq     = out_idx + (size_t)BATCH * TDIM;            // B*C*T

    cudaFuncSetAttribute(gemm_proj_all,
                         cudaFuncAttributeMaxDynamicSharedMemorySize, GEMM_SMEM);
    cudaFuncSetAttribute(gemm_logits_mma,
                         cudaFuncAttributeMaxDynamicSharedMemorySize, GEMM_SMEM);

    // prep: cb split + W transpose-splits (one launch)
    prep_split_kernel<<<2048 + 768, 256>>>(cb, Wq, Wk, Wv);
    // hidden transpose-split with fused head-gate computation
    hsplit_cg_kernel<<<dim3(TDIM / 32, BATCH), 256>>>(hidden, Wp, bp);
    // all projections in one launch (tile 128x128)
    gemm_proj_all<<<dim3(4, 128), 256, GEMM_SMEM>>>(bq, bk, bv);
    // logits + fused argmax partials
    gemm_logits_mma<<<dim3(TDIM / 128, NCB / 128, BATCH), 256, GEMM_SMEM>>>(out_logits);
    // fused final argmax + z_q gather
    argmax_zq_kernel<<<dim3(TDIM / 32, BATCH), 256>>>(out_idx, out_zq);
}